// round 2
// baseline (speedup 1.0000x reference)
#include <cuda_runtime.h>

// Problem constants (fixed shapes for this problem instance)
#define NROWS 2048
#define DFEAT 128
#define NT    32
#define TILE  64
#define XS    65   // padded stride for transposed X tiles [d][row]
#define PS    65   // padded stride for transposed pred tiles [t][row]

static const int SMEM_BYTES = (2 * DFEAT * XS + 2 * NT * PS) * (int)sizeof(float); // 83200

__device__ float  g_rnorm[NROWS];
__device__ double g_acc;

// ---------------------------------------------------------------------------
// Kernel 1: per-row inverse norms of X; also zero the global accumulator.
// One warp per row. 256 threads/block -> 8 rows/block -> 256 blocks.
// ---------------------------------------------------------------------------
__global__ void norm_kernel(const float* __restrict__ X) {
    if (blockIdx.x == 0 && threadIdx.x == 0) g_acc = 0.0;
    int warp = (blockIdx.x * blockDim.x + threadIdx.x) >> 5;
    int lane = threadIdx.x & 31;
    if (warp >= NROWS) return;
    const float4* row = (const float4*)(X + (size_t)warp * DFEAT);
    float4 v = row[lane];                       // 32 lanes * 4 = 128 elems
    float s = v.x * v.x + v.y * v.y + v.z * v.z + v.w * v.w;
    #pragma unroll
    for (int o = 16; o > 0; o >>= 1) s += __shfl_xor_sync(0xffffffffu, s, o);
    if (lane == 0) g_rnorm[warp] = rsqrtf(s);
}

// ---------------------------------------------------------------------------
// Kernel 2: fused cosine-distance + hinge over 64x64 pair tiles.
// Grid (32, 32): blockIdx.x = k-tile, blockIdx.y = j-tile; tk < tj exits.
// 256 threads as 16x16; each thread owns a 4x4 strided sub-block
// (j = ty + 16*jr, k = tx + 16*kr).
// ---------------------------------------------------------------------------
__global__ void __launch_bounds__(256, 2)
pair_kernel(const float* __restrict__ X,
            const float* __restrict__ P,
            const float* __restrict__ scale_p) {
    const int tk = blockIdx.x;
    const int tj = blockIdx.y;
    if (tk < tj) return;

    extern __shared__ float sm[];
    float* sXj = sm;                     // [DFEAT][XS]  transposed, normalized
    float* sXk = sXj + DFEAT * XS;       // [DFEAT][XS]
    float* sPj = sXk + DFEAT * XS;       // [NT][PS]     transposed
    float* sPk = sPj + NT * PS;          // [NT][PS]

    const int tid = threadIdx.x;
    const int j0 = tj * TILE;
    const int k0 = tk * TILE;
    const float scale = *scale_p;

    // Load X tiles: transpose + normalize on the fly.
    // Warp lanes walk d for a fixed row -> store bank = (d + row) % 32, conflict-free.
    for (int i = tid; i < TILE * DFEAT; i += 256) {
        int row = i >> 7;        // /128
        int d   = i & 127;
        sXj[d * XS + row] = X[(size_t)(j0 + row) * DFEAT + d] * g_rnorm[j0 + row];
        sXk[d * XS + row] = X[(size_t)(k0 + row) * DFEAT + d] * g_rnorm[k0 + row];
    }
    // Load prediction tiles (transposed).
    for (int i = tid; i < TILE * NT; i += 256) {
        int row = i >> 5;        // /32
        int t   = i & 31;
        sPj[t * PS + row] = P[(size_t)(j0 + row) * NT + t];
        sPk[t * PS + row] = P[(size_t)(k0 + row) * NT + t];
    }
    __syncthreads();

    const int tx = tid & 15;
    const int ty = tid >> 4;

    // ---- cosine dot products: acc[jr][kr] = Xn_j . Xn_k ----
    float acc[4][4];
    #pragma unroll
    for (int a = 0; a < 4; a++)
        #pragma unroll
        for (int b = 0; b < 4; b++) acc[a][b] = 0.0f;

    #pragma unroll 8
    for (int d = 0; d < DFEAT; d++) {
        float aj[4], bk[4];
        #pragma unroll
        for (int r = 0; r < 4; r++) {
            aj[r] = sXj[d * XS + ty + 16 * r];
            bk[r] = sXk[d * XS + tx + 16 * r];
        }
        #pragma unroll
        for (int jr = 0; jr < 4; jr++)
            #pragma unroll
            for (int kr = 0; kr < 4; kr++)
                acc[jr][kr] += aj[jr] * bk[kr];
    }

    // thresholds c = scale * dist; invalid pairs (k <= j) get a huge threshold
    float c[4][4];
    #pragma unroll
    for (int jr = 0; jr < 4; jr++) {
        int gj = j0 + ty + 16 * jr;
        #pragma unroll
        for (int kr = 0; kr < 4; kr++) {
            int gk = k0 + tx + 16 * kr;
            c[jr][kr] = (gk > gj) ? scale * (1.0f - acc[jr][kr]) : 1.0e30f;
        }
    }

    // ---- hinge accumulation over time points ----
    float hsum = 0.0f;
    #pragma unroll 4
    for (int t = 0; t < NT; t++) {
        float pj[4], pk[4];
        #pragma unroll
        for (int r = 0; r < 4; r++) {
            pj[r] = sPj[t * PS + ty + 16 * r];
            pk[r] = sPk[t * PS + tx + 16 * r];
        }
        #pragma unroll
        for (int jr = 0; jr < 4; jr++)
            #pragma unroll
            for (int kr = 0; kr < 4; kr++)
                hsum += fmaxf(fabsf(pj[jr] - pk[kr]) - c[jr][kr], 0.0f);
    }

    // ---- block reduction ----
    #pragma unroll
    for (int o = 16; o > 0; o >>= 1) hsum += __shfl_xor_sync(0xffffffffu, hsum, o);

    __shared__ float red[8];
    if ((tid & 31) == 0) red[tid >> 5] = hsum;
    __syncthreads();
    if (tid == 0) {
        float bs = 0.0f;
        #pragma unroll
        for (int w = 0; w < 8; w++) bs += red[w];
        atomicAdd(&g_acc, (double)bs);
    }
}

// ---------------------------------------------------------------------------
// Kernel 3: scalar epilogue.
// ---------------------------------------------------------------------------
__global__ void fin_kernel(const float* __restrict__ target, float* __restrict__ out) {
    double R  = g_acc;
    double mf = 2.0 * R / ((double)NROWS * (double)(NROWS - 1) * (double)NT);
    float  r  = (float)mf - *target;
    out[0] = fmaxf(r, 0.0f);
}

// ---------------------------------------------------------------------------
extern "C" void kernel_launch(void* const* d_in, const int* in_sizes, int n_in,
                              void* d_out, int out_size) {
    const float* target = (const float*)d_in[0];
    const float* pred   = (const float*)d_in[1];
    const float* X      = (const float*)d_in[2];
    // d_in[3] = ntimes (compile-time constant NT here)
    const float* scale  = (const float*)d_in[4];
    float* out = (float*)d_out;

    cudaFuncSetAttribute(pair_kernel,
                         cudaFuncAttributeMaxDynamicSharedMemorySize, SMEM_BYTES);

    norm_kernel<<<NROWS / 8, 256>>>(X);
    dim3 grid(NROWS / TILE, NROWS / TILE);   // (32, 32), upper triangle active
    pair_kernel<<<grid, 256, SMEM_BYTES>>>(X, pred, scale);
    fin_kernel<<<1, 1>>>(target, out);
}